// round 8
// baseline (speedup 1.0000x reference)
#include <cuda_runtime.h>

// fm: (1, 256, 256, 256) fp32 NHWC; rois: (2000, 5) int32 [b, x, y, w, h]; pool = 7.
#define FM_W 256
#define FM_C 256
#define POOLSZ 7
#define NCELL (POOLSZ * POOLSZ)
#define RPB 2                      // ROIs per block -> grid 1000, single wave

__global__ __launch_bounds__(256, 8) void roi_pool_kernel(
    const float* __restrict__ fm,      // [H, W, C]
    const int* __restrict__ rois,      // [N, 5]
    float* __restrict__ out,           // [N, 7, 7, C]
    int n_rois)
{
    int roi0 = blockIdx.x * RPB;
    int tid = threadIdx.x;

    // 16B-aligned element types: the broadcast LDS.128 reads require it.
    __shared__ int4   sIdx[RPB][NCELL];   // float4-unit base index of the 4 corners
    __shared__ float4 sWt[RPB][NCELL];    // fused bilinear weights

    // Setup: threads 0..97 each build one (roi-slot, cell) entry, computing
    // both axes inline. One barrier for the whole kernel.
    if (tid < RPB * NCELL) {
        int slot = tid / NCELL;            // 0..1
        int cell = tid - slot * NCELL;     // 0..48
        int roi  = roi0 + slot;
        if (roi < n_rois) {
            int rx = rois[roi * 5 + 1];
            int ry = rois[roi * 5 + 2];
            int rw = rois[roi * 5 + 3];
            int rh = rois[roi * 5 + 4];

            int py = cell / POOLSZ;
            int px = cell - py * POOLSZ;

            float lh = (float)rh;
            float fyc = ((float)py + 0.5f) * (lh / (float)POOLSZ) - 0.5f;
            fyc = fminf(fmaxf(fyc, 0.0f), lh - 1.0f);
            int iy0 = (int)floorf(fyc);
            int iy1 = min(iy0 + 1, rh - 1);
            float fy = fyc - (float)iy0;

            float lw = (float)rw;
            float fxc = ((float)px + 0.5f) * (lw / (float)POOLSZ) - 0.5f;
            fxc = fminf(fmaxf(fxc, 0.0f), lw - 1.0f);
            int ix0 = (int)floorf(fxc);
            int ix1 = min(ix0 + 1, rw - 1);
            float fx = fxc - (float)ix0;

            int y0 = ry + iy0, y1 = ry + iy1;
            int x0 = rx + ix0, x1 = rx + ix1;

            int4 idx;
            idx.x = (y0 * FM_W + x0) * (FM_C / 4);
            idx.y = (y0 * FM_W + x1) * (FM_C / 4);
            idx.z = (y1 * FM_W + x0) * (FM_C / 4);
            idx.w = (y1 * FM_W + x1) * (FM_C / 4);
            sIdx[slot][cell] = idx;

            float ofx = 1.0f - fx, ofy = 1.0f - fy;
            float4 w;
            w.x = ofx * ofy;
            w.y = fx  * ofy;
            w.z = ofx * fy;
            w.w = fx  * fy;
            sWt[slot][cell] = w;
        }
    }
    __syncthreads();

    int c  = tid & 63;        // channel float4 index 0..63
    int ty = tid >> 6;        // cell-group 0..3

    const float4* f4 = (const float4*)fm;
    float4* o4 = (float4*)out + (size_t)roi0 * NCELL * (FM_C / 4);

    int n_cells = min(n_rois - roi0, RPB) * NCELL;   // 98 normally

    #pragma unroll 4
    for (int g = ty; g < n_cells; g += 4) {
        int slot = (g >= NCELL);                 // 0 or 1
        int cell = g - (slot ? NCELL : 0);

        int4   idx = sIdx[slot][cell];           // broadcast LDS.128
        float4 w   = sWt[slot][cell];            // broadcast LDS.128

        const float4 g00 = __ldg(f4 + idx.x + c);
        const float4 g01 = __ldg(f4 + idx.y + c);
        const float4 g10 = __ldg(f4 + idx.z + c);
        const float4 g11 = __ldg(f4 + idx.w + c);

        float4 r;
        r.x = g00.x * w.x + g01.x * w.y + g10.x * w.z + g11.x * w.w;
        r.y = g00.y * w.x + g01.y * w.y + g10.y * w.z + g11.y * w.w;
        r.z = g00.z * w.x + g01.z * w.y + g10.z * w.z + g11.z * w.w;
        r.w = g00.w * w.x + g01.w * w.y + g10.w * w.z + g11.w * w.w;

        // Streaming store: output written once, never read — evict first.
        __stcs(&o4[g * (FM_C / 4) + c], r);
    }
}

extern "C" void kernel_launch(void* const* d_in, const int* in_sizes, int n_in,
                              void* d_out, int out_size)
{
    const float* fm  = (const float*)d_in[0];
    const int* rois  = (const int*)d_in[1];
    float* out       = (float*)d_out;

    int n_rois = in_sizes[1] / 5;
    int grid = (n_rois + RPB - 1) / RPB;

    roi_pool_kernel<<<grid, 256>>>(fm, rois, out, n_rois);
}

// round 9
// speedup vs baseline: 1.0538x; 1.0538x over previous
#include <cuda_runtime.h>

// fm: (1, 256, 256, 256) fp32 NHWC; rois: (2000, 5) int32 [b, x, y, w, h]; pool = 7.
#define FM_W 256
#define FM_C 256
#define POOLSZ 7
#define NCELL (POOLSZ * POOLSZ)

__global__ __launch_bounds__(256) void roi_pool_kernel(
    const float* __restrict__ fm,      // [H, W, C]
    const int* __restrict__ rois,      // [N, 5]
    float* __restrict__ out)           // [N, 7, 7, C]
{
    int roi = blockIdx.x;
    int tid = threadIdx.x;

    __shared__ int   sx0[POOLSZ], sx1[POOLSZ], sy0[POOLSZ], sy1[POOLSZ];
    __shared__ float sfx[POOLSZ], sfy[POOLSZ];
    __shared__ int4   sIdx[NCELL];   // 16B-aligned: float4-unit corner base indices
    __shared__ float4 sWt[NCELL];    // fused bilinear weights w00,w01,w10,w11

    if (tid < 2 * POOLSZ) {
        int  p   = (tid >= POOLSZ) ? tid - POOLSZ : tid;
        bool isx = tid < POOLSZ;
        int start = rois[roi * 5 + (isx ? 1 : 2)];
        int len   = rois[roi * 5 + (isx ? 3 : 4)];
        float lf = (float)len;
        float f = ((float)p + 0.5f) * (lf / (float)POOLSZ) - 0.5f;
        f = fminf(fmaxf(f, 0.0f), lf - 1.0f);
        int i0 = (int)floorf(f);
        int i1 = min(i0 + 1, len - 1);
        float fr = f - (float)i0;
        if (isx) { sx0[p] = start + i0; sx1[p] = start + i1; sfx[p] = fr; }
        else     { sy0[p] = start + i0; sy1[p] = start + i1; sfy[p] = fr; }
    }
    __syncthreads();

    if (tid < NCELL) {
        int py = tid / POOLSZ;
        int px = tid - py * POOLSZ;
        int y0 = sy0[py], y1 = sy1[py];
        int x0 = sx0[px], x1 = sx1[px];
        float fy = sfy[py], fx = sfx[px];
        float ofx = 1.0f - fx, ofy = 1.0f - fy;
        int4 idx;
        idx.x = (y0 * FM_W + x0) * (FM_C / 4);
        idx.y = (y0 * FM_W + x1) * (FM_C / 4);
        idx.z = (y1 * FM_W + x0) * (FM_C / 4);
        idx.w = (y1 * FM_W + x1) * (FM_C / 4);
        sIdx[tid] = idx;
        float4 w;
        w.x = ofx * ofy;
        w.y = fx  * ofy;
        w.z = ofx * fy;
        w.w = fx  * fy;
        sWt[tid] = w;
    }
    __syncthreads();

    int c  = tid & 63;        // channel float4 index 0..63
    int ty = tid >> 6;        // cell-group 0..3

    const float4* f4 = (const float4*)fm;
    float4* o4 = (float4*)out + (size_t)roi * NCELL * (FM_C / 4);

    // Manual 2-cell software pipeline: all 8 corner loads issued before any
    // FMA/store -> MLP_p1 = 8 per thread, hiding the ~250cyc L2-hit latency.
    for (int c0 = ty; c0 < NCELL; c0 += 8) {
        int c1 = c0 + 4;
        bool has1 = (c1 < NCELL);
        int c1s = has1 ? c1 : c0;        // safe index for the speculative loads

        int4   idxA = sIdx[c0];
        int4   idxB = sIdx[c1s];
        float4 wA   = sWt[c0];
        float4 wB   = sWt[c1s];

        // 8 independent loads, back to back.
        const float4 a00 = __ldg(f4 + idxA.x + c);
        const float4 a01 = __ldg(f4 + idxA.y + c);
        const float4 a10 = __ldg(f4 + idxA.z + c);
        const float4 a11 = __ldg(f4 + idxA.w + c);
        const float4 b00 = __ldg(f4 + idxB.x + c);
        const float4 b01 = __ldg(f4 + idxB.y + c);
        const float4 b10 = __ldg(f4 + idxB.z + c);
        const float4 b11 = __ldg(f4 + idxB.w + c);

        float4 rA;
        rA.x = a00.x * wA.x + a01.x * wA.y + a10.x * wA.z + a11.x * wA.w;
        rA.y = a00.y * wA.x + a01.y * wA.y + a10.y * wA.z + a11.y * wA.w;
        rA.z = a00.z * wA.x + a01.z * wA.y + a10.z * wA.z + a11.z * wA.w;
        rA.w = a00.w * wA.x + a01.w * wA.y + a10.w * wA.z + a11.w * wA.w;
        __stcs(&o4[c0 * (FM_C / 4) + c], rA);

        if (has1) {
            float4 rB;
            rB.x = b00.x * wB.x + b01.x * wB.y + b10.x * wB.z + b11.x * wB.w;
            rB.y = b00.y * wB.x + b01.y * wB.y + b10.y * wB.z + b11.y * wB.w;
            rB.z = b00.z * wB.x + b01.z * wB.y + b10.z * wB.z + b11.z * wB.w;
            rB.w = b00.w * wB.x + b01.w * wB.y + b10.w * wB.z + b11.w * wB.w;
            __stcs(&o4[c1 * (FM_C / 4) + c], rB);
        }
    }
}

extern "C" void kernel_launch(void* const* d_in, const int* in_sizes, int n_in,
                              void* d_out, int out_size)
{
    const float* fm  = (const float*)d_in[0];
    const int* rois  = (const int*)d_in[1];
    float* out       = (float*)d_out;

    int n_rois = in_sizes[1] / 5;

    roi_pool_kernel<<<n_rois, 256>>>(fm, rois, out);
}